// round 7
// baseline (speedup 1.0000x reference)
#include <cuda_runtime.h>
#include <math.h>

// Problem constants (fixed by the dataset)
#define N_NODES 40000
#define N_EDGES 640000
#define DIM     128
#define OUTD    64
#define NGRAPH  64
#define SCAN_B  40            // ceil(40000/1024)
#define EQT     160000        // N_EDGES / 4 (edges per thread-quarter)

// ---------------- device scratch (no allocation allowed) ----------------
__device__ float g_t[N_NODES * DIM];     // GEMM output (pre-aggregation features)
__device__ float g_h[N_NODES * DIM];     // layer output (post relu)
__device__ int   g_cnt[N_NODES];         // in-degree counts
__device__ int   g_rowptr[N_NODES + 1];  // CSR row pointers (by dst)
__device__ int   g_cursor[N_NODES];      // scatter cursors
__device__ int   g_col[N_EDGES];         // CSR col (src) indices
__device__ float g_dinv[N_NODES];        // 1/sqrt(deg+1)
__device__ int   g_is64;                 // 1 if indices are int64, 0 if int32
// packed lookback state: high 32 = flag (0 invalid/1 partial/2 prefix), low 32 = value.
__device__ volatile unsigned long long g_scan_pkt[SCAN_B];

// ---------------- f32x2 packed-math helpers (Blackwell FFMA2) -------------
__device__ __forceinline__ unsigned long long pack2(float lo, float hi) {
    unsigned long long d;
    asm("mov.b64 %0, {%1, %2};" : "=l"(d) : "f"(lo), "f"(hi));
    return d;
}
__device__ __forceinline__ unsigned long long ffma2(unsigned long long a,
                                                    unsigned long long b,
                                                    unsigned long long c) {
    unsigned long long d;
    asm("fma.rn.f32x2 %0, %1, %2, %3;" : "=l"(d) : "l"(a), "l"(b), "l"(c));
    return d;
}
__device__ __forceinline__ float2 unpack2(unsigned long long v) {
    float lo, hi;
    asm("mov.b64 {%0, %1}, %2;" : "=f"(lo), "=f"(hi) : "l"(v));
    return make_float2(lo, hi);
}

// Uniform index load honoring detected dtype.
__device__ __forceinline__ int load_idx(const void* p, int i) {
    if (g_is64) return (int)((const long long*)p)[i];
    return ((const int*)p)[i];
}

// ---------------- init (+ dtype detection + scan-state reset) -------------
__global__ void init_kernel(const void* __restrict__ ei) {
    int i = blockIdx.x * blockDim.x + threadIdx.x;
    if (i == 0) {
        const long long* p = (const long long*)ei;
        int ok = 1;
        #pragma unroll
        for (int q = 0; q < 16; ++q) {
            long long v = p[q];
            if (v < 0 || v >= N_NODES) ok = 0;
        }
        g_is64 = ok;
    }
    if (i < SCAN_B) g_scan_pkt[i] = 0ull;
    if (i < N_NODES) g_cnt[i] = 0;
}

// ---------------- degree count: 4 edges/thread (independent atomic chains)
__global__ __launch_bounds__(256) void count_kernel(const void* __restrict__ ei) {
    int t = blockIdx.x * 256 + threadIdx.x;
    if (t < EQT) {
        #pragma unroll
        for (int q = 0; q < 4; ++q) {
            int e = t + q * EQT;
            int dst = load_idx(ei, N_EDGES + e);
            atomicAdd(&g_cnt[dst], 1);
        }
    }
}

// ---------------- single-pass scan with warp-parallel lookback ------------
__global__ __launch_bounds__(1024) void scan_kernel() {
    __shared__ int wsum[32];
    __shared__ int s_off;
    int tid = threadIdx.x, lane = tid & 31, w = tid >> 5;
    int b = blockIdx.x;
    int i = b * 1024 + tid;
    int v = (i < N_NODES) ? g_cnt[i] : 0;

    // block-local inclusive scan
    int incl = v;
    #pragma unroll
    for (int off = 1; off < 32; off <<= 1) {
        int t = __shfl_up_sync(0xffffffffu, incl, off);
        if (lane >= off) incl += t;
    }
    if (lane == 31) wsum[w] = incl;
    __syncthreads();
    if (w == 0) {
        int s = wsum[lane];
        #pragma unroll
        for (int off = 1; off < 32; off <<= 1) {
            int t = __shfl_up_sync(0xffffffffu, s, off);
            if (lane >= off) s += t;
        }
        wsum[lane] = s;
    }
    __syncthreads();
    int pref = (w > 0) ? wsum[w - 1] : 0;
    int blkIncl = incl + pref;
    int blkTotal = wsum[31];

    // decoupled lookback, warp 0, 32 predecessors per poll window
    if (w == 0) {
        if (b == 0) {
            if (lane == 0) {
                g_scan_pkt[0] = (2ull << 32) | (unsigned)blkTotal;
                s_off = 0;
            }
        } else {
            if (lane == 0) g_scan_pkt[b] = (1ull << 32) | (unsigned)blkTotal;
            int sum = 0;
            int look = b - 1;
            for (;;) {
                int p = look - lane;
                unsigned long long pkt; int flag;
                if (p >= 0) {
                    do { pkt = g_scan_pkt[p]; flag = (int)(pkt >> 32); } while (flag == 0);
                } else { pkt = (2ull << 32); flag = 2; }
                unsigned mask = __ballot_sync(0xffffffffu, flag == 2);
                int firstP = mask ? (__ffs(mask) - 1) : 31;
                int val = (lane <= firstP) ? (int)(unsigned)pkt : 0;
                #pragma unroll
                for (int off = 16; off > 0; off >>= 1)
                    val += __shfl_down_sync(0xffffffffu, val, off);
                if (lane == 0) sum += val;
                if (mask) break;
                look -= 32;
            }
            if (lane == 0) {
                g_scan_pkt[b] = (2ull << 32) | (unsigned)(sum + blkTotal);
                s_off = sum;
            }
        }
    }
    __syncthreads();
    int offset = s_off;

    int inclTot = blkIncl + offset;
    if (i < N_NODES) {
        g_rowptr[i + 1] = inclTot;
        g_cursor[i] = inclTot - v;
        g_dinv[i] = rsqrtf((float)v + 1.0f);
        if (i == 0) g_rowptr[0] = 0;
    }
}

// ---------------- CSR fill: 4 edges/thread ----------------
__global__ __launch_bounds__(256) void fill_kernel(const void* __restrict__ ei) {
    int t = blockIdx.x * 256 + threadIdx.x;
    if (t < EQT) {
        #pragma unroll
        for (int q = 0; q < 4; ++q) {
            int e = t + q * EQT;
            int src = load_idx(ei, e);
            int dst = load_idx(ei, N_EDGES + e);
            int pos = atomicAdd(&g_cursor[dst], 1);
            g_col[pos] = src;
        }
    }
}

// ---------------- SGEMM with FFMA2: g_t = A(40000x128) @ W(128x128) -------
// Block tile 64x128, 128 threads, 8x8 microtile as 8x(4 f32x2) per thread.
__global__ __launch_bounds__(128) void gemm_kernel(const float* __restrict__ Ain,
                                                   const float* __restrict__ W) {
    const float* A = Ain ? Ain : g_h;
    __shared__ float As[32][68];    // [k][m], padded
    __shared__ float Bs[32][128];   // [k][n]

    int tid  = threadIdx.x;
    int tcol = tid & 15;
    int trow = tid >> 4;
    int row0 = blockIdx.x * 64;

    unsigned long long acc2[8][4];
    #pragma unroll
    for (int i = 0; i < 8; ++i)
        #pragma unroll
        for (int p = 0; p < 4; ++p) acc2[i][p] = 0ull;   // bit pattern = (0.f, 0.f)

    for (int kt = 0; kt < 4; ++kt) {
        {
            int m  = tid >> 1;
            int k0 = (tid & 1) * 16;
            const float* ap = &A[(size_t)(row0 + m) * DIM + kt * 32 + k0];
            #pragma unroll
            for (int q = 0; q < 4; ++q) {
                float4 a = *(const float4*)(ap + q * 4);
                As[k0 + q * 4 + 0][m] = a.x;
                As[k0 + q * 4 + 1][m] = a.y;
                As[k0 + q * 4 + 2][m] = a.z;
                As[k0 + q * 4 + 3][m] = a.w;
            }
        }
        #pragma unroll
        for (int i = 0; i < 8; ++i) {
            int f  = tid + i * 128;
            int kk = f >> 5;
            int nn = (f & 31) * 4;
            *(float4*)&Bs[kk][nn] = *(const float4*)&W[(kt * 32 + kk) * DIM + nn];
        }
        __syncthreads();

        #pragma unroll
        for (int k = 0; k < 32; ++k) {
            float4 a0 = *(const float4*)&As[k][trow * 8];
            float4 a1 = *(const float4*)&As[k][trow * 8 + 4];
            float4 b0 = *(const float4*)&Bs[k][tcol * 8];
            float4 b1 = *(const float4*)&Bs[k][tcol * 8 + 4];
            unsigned long long bv2[4];
            bv2[0] = pack2(b0.x, b0.y);
            bv2[1] = pack2(b0.z, b0.w);
            bv2[2] = pack2(b1.x, b1.y);
            bv2[3] = pack2(b1.z, b1.w);
            float av[8] = {a0.x, a0.y, a0.z, a0.w, a1.x, a1.y, a1.z, a1.w};
            #pragma unroll
            for (int i = 0; i < 8; ++i) {
                unsigned long long a2 = pack2(av[i], av[i]);
                #pragma unroll
                for (int p = 0; p < 4; ++p)
                    acc2[i][p] = ffma2(a2, bv2[p], acc2[i][p]);
            }
        }
        __syncthreads();
    }

    #pragma unroll
    for (int i = 0; i < 8; ++i) {
        int r = row0 + trow * 8 + i;
        float2 c0 = unpack2(acc2[i][0]);
        float2 c1 = unpack2(acc2[i][1]);
        float2 c2 = unpack2(acc2[i][2]);
        float2 c3 = unpack2(acc2[i][3]);
        float4 v0 = make_float4(c0.x, c0.y, c1.x, c1.y);
        float4 v1 = make_float4(c2.x, c2.y, c3.x, c3.y);
        *(float4*)&g_t[(size_t)r * DIM + tcol * 8]     = v0;
        *(float4*)&g_t[(size_t)r * DIM + tcol * 8 + 4] = v1;
    }
}

// ---------------- aggregation: warp-per-node, float4 gathers --------------
__global__ __launch_bounds__(256) void agg_kernel(const float* __restrict__ bias) {
    int warp = threadIdx.x >> 5;
    int lane = threadIdx.x & 31;
    int i = blockIdx.x * 8 + warp;

    float di = g_dinv[i];
    const float4 tself = *(const float4*)&g_t[(size_t)i * DIM + lane * 4];
    float4 acc;
    acc.x = di * di * tself.x;
    acc.y = di * di * tself.y;
    acc.z = di * di * tself.z;
    acc.w = di * di * tself.w;

    int s = g_rowptr[i], e = g_rowptr[i + 1];
    for (int base = s; base < e; base += 32) {
        int n = min(32, e - base);
        int c = 0; float wgt = 0.f;
        if (lane < n) {
            c = g_col[base + lane];
            wgt = g_dinv[c] * di;
        }
        #pragma unroll 8
        for (int j = 0; j < n; ++j) {
            int   cj = __shfl_sync(0xffffffffu, c, j);
            float wj = __shfl_sync(0xffffffffu, wgt, j);
            const float4 v = *(const float4*)&g_t[(size_t)cj * DIM + lane * 4];
            acc.x = fmaf(wj, v.x, acc.x);
            acc.y = fmaf(wj, v.y, acc.y);
            acc.z = fmaf(wj, v.z, acc.z);
            acc.w = fmaf(wj, v.w, acc.w);
        }
    }

    const float4 b4 = *(const float4*)&bias[lane * 4];
    float4 r;
    r.x = fmaxf(acc.x + b4.x, 0.f);
    r.y = fmaxf(acc.y + b4.y, 0.f);
    r.z = fmaxf(acc.z + b4.z, 0.f);
    r.w = fmaxf(acc.w + b4.w, 0.f);
    *(float4*)&g_h[(size_t)i * DIM + lane * 4] = r;
}

// ---------------- fused pool + linear + L2 normalize ----------------------
__global__ __launch_bounds__(128) void poolfinal_kernel(const void* __restrict__ batch,
                                                        const float* __restrict__ Wl,
                                                        const float* __restrict__ bl,
                                                        float* __restrict__ out) {
    int g = blockIdx.x;
    int tid = threadIdx.x;
    __shared__ int s_lo, s_hi;
    __shared__ float mean[DIM];
    __shared__ float outv[OUTD];
    __shared__ float red[OUTD];

    if (tid == 0 || tid == 1) {
        int target = g + tid;
        int lo = 0, hi = N_NODES;
        while (lo < hi) {
            int mid = (lo + hi) >> 1;
            if (load_idx(batch, mid) < target) lo = mid + 1;
            else hi = mid;
        }
        if (tid == 0) s_lo = lo; else s_hi = lo;
    }
    __syncthreads();
    int lo = s_lo, hi = s_hi;

    float s0 = 0.f, s1 = 0.f, s2 = 0.f, s3 = 0.f;
    int n = lo;
    for (; n + 4 <= hi; n += 4) {
        s0 += g_h[(size_t)(n + 0) * DIM + tid];
        s1 += g_h[(size_t)(n + 1) * DIM + tid];
        s2 += g_h[(size_t)(n + 2) * DIM + tid];
        s3 += g_h[(size_t)(n + 3) * DIM + tid];
    }
    for (; n < hi; ++n) s0 += g_h[(size_t)n * DIM + tid];
    float sum = (s0 + s1) + (s2 + s3);
    float cn = fmaxf((float)(hi - lo), 1.f);
    mean[tid] = sum / cn;
    __syncthreads();

    if (tid < OUTD) {
        float acc = bl[tid];
        #pragma unroll
        for (int h = 0; h < DIM; ++h)
            acc = fmaf(mean[h], Wl[h * OUTD + tid], acc);
        outv[tid] = acc;
        red[tid]  = acc * acc;
    }
    __syncthreads();
    for (int s = 32; s > 0; s >>= 1) {
        if (tid < s && tid + s < OUTD) red[tid] += red[tid + s];
        __syncthreads();
    }
    if (tid < OUTD) {
        float nrm = sqrtf(red[0]);
        out[g * OUTD + tid] = outv[tid] / fmaxf(nrm, 1e-12f);
    }
}

// ---------------- launch ----------------
extern "C" void kernel_launch(void* const* d_in, const int* in_sizes, int n_in,
                              void* d_out, int out_size) {
    const float* x     = (const float*)d_in[0];
    const float* W1    = (const float*)d_in[1];
    const float* b1    = (const float*)d_in[2];
    const float* W2    = (const float*)d_in[3];
    const float* b2    = (const float*)d_in[4];
    const float* Wl    = (const float*)d_in[5];
    const float* bl    = (const float*)d_in[6];
    const void*  ei    = d_in[7];
    const void*  batch = d_in[8];
    float* out = (float*)d_out;

    init_kernel<<<(N_NODES + 255) / 256, 256>>>(ei);
    count_kernel<<<(EQT + 255) / 256, 256>>>(ei);
    scan_kernel<<<SCAN_B, 1024>>>();
    fill_kernel<<<(EQT + 255) / 256, 256>>>(ei);

    // layer 1
    gemm_kernel<<<N_NODES / 64, 128>>>(x, W1);
    agg_kernel<<<N_NODES / 8, 256>>>(b1);
    // layer 2
    gemm_kernel<<<N_NODES / 64, 128>>>(nullptr, W2);
    agg_kernel<<<N_NODES / 8, 256>>>(b2);

    poolfinal_kernel<<<NGRAPH, 128>>>(batch, Wl, bl, out);
}

// round 9
// speedup vs baseline: 1.1732x; 1.1732x over previous
#include <cuda_runtime.h>
#include <cuda_bf16.h>
#include <math.h>
#include <stdint.h>

// Problem constants (fixed by the dataset)
#define N_NODES 40000
#define N_EDGES 640000
#define DIM     128
#define OUTD    64
#define NGRAPH  64
#define SCAN_B  40            // ceil(40000/1024)
#define GTILES  313           // ceil(40000/128)

// ---------------- device scratch (no allocation allowed) ----------------
__device__ float g_t[N_NODES * DIM];     // GEMM output (pre-aggregation features)
__device__ float g_h[N_NODES * DIM];     // layer output (post relu)
__device__ int   g_cnt[N_NODES];         // in-degree counts
__device__ int   g_rowptr[N_NODES + 1];  // CSR row pointers (by dst)
__device__ int   g_cursor[N_NODES];      // scatter cursors
__device__ int   g_col[N_EDGES];         // CSR col (src) indices
__device__ float g_dinv[N_NODES];        // 1/sqrt(deg+1)
__device__ int   g_is64;                 // 1 if indices are int64, 0 if int32
__device__ int   g_bsum[SCAN_B];
__device__ int   g_boff[SCAN_B];

// ---------------- helpers ----------------
__device__ __forceinline__ uint32_t smem_u32(const void* p) {
    uint32_t a;
    asm("{ .reg .u64 t; cvta.to.shared.u64 t, %1; cvt.u32.u64 %0, t; }"
        : "=r"(a) : "l"(p));
    return a;
}
__device__ __forceinline__ uint32_t cvt_bf16x2(float hi, float lo) {
    uint32_t r;
    asm("cvt.rn.bf16x2.f32 %0, %1, %2;" : "=r"(r) : "f"(hi), "f"(lo));
    return r;
}
__device__ __forceinline__ void ldsm_x4(uint32_t r[4], uint32_t addr) {
    asm volatile("ldmatrix.sync.aligned.m8n8.x4.shared.b16 {%0,%1,%2,%3}, [%4];"
        : "=r"(r[0]), "=r"(r[1]), "=r"(r[2]), "=r"(r[3]) : "r"(addr));
}
__device__ __forceinline__ void ldsm_x4_t(uint32_t r[4], uint32_t addr) {
    asm volatile("ldmatrix.sync.aligned.m8n8.x4.trans.shared.b16 {%0,%1,%2,%3}, [%4];"
        : "=r"(r[0]), "=r"(r[1]), "=r"(r[2]), "=r"(r[3]) : "r"(addr));
}
__device__ __forceinline__ void mma_bf16(float c[4], const uint32_t a[4],
                                         const uint32_t b0, const uint32_t b1) {
    asm volatile(
        "mma.sync.aligned.m16n8k16.row.col.f32.bf16.bf16.f32 "
        "{%0,%1,%2,%3}, {%4,%5,%6,%7}, {%8,%9}, {%0,%1,%2,%3};"
        : "+f"(c[0]), "+f"(c[1]), "+f"(c[2]), "+f"(c[3])
        : "r"(a[0]), "r"(a[1]), "r"(a[2]), "r"(a[3]), "r"(b0), "r"(b1));
}

// Uniform index load honoring detected dtype.
__device__ __forceinline__ int load_idx(const void* p, int i) {
    if (g_is64) return (int)((const long long*)p)[i];
    return ((const int*)p)[i];
}

// ---------------- init (+ dtype detection) --------------------------------
__global__ void init_kernel(const void* __restrict__ ei) {
    int i = blockIdx.x * blockDim.x + threadIdx.x;
    if (i == 0) {
        const long long* p = (const long long*)ei;
        int ok = 1;
        #pragma unroll
        for (int q = 0; q < 16; ++q) {
            long long v = p[q];
            if (v < 0 || v >= N_NODES) ok = 0;
        }
        g_is64 = ok;
    }
    if (i < N_NODES) g_cnt[i] = 0;
}

// ---------------- degree count ----------------
__global__ __launch_bounds__(512) void count_kernel(const void* __restrict__ ei) {
    int e = blockIdx.x * blockDim.x + threadIdx.x;
    if (e < N_EDGES) {
        int dst = load_idx(ei, N_EDGES + e);
        atomicAdd(&g_cnt[dst], 1);
    }
}

// ---------------- 3-pass scan (round-4 validated) --------------------------
__global__ __launch_bounds__(1024) void scan1_kernel() {
    __shared__ int wsum[32];
    int tid = threadIdx.x, lane = tid & 31, w = tid >> 5;
    int i = blockIdx.x * 1024 + tid;
    int v = (i < N_NODES) ? g_cnt[i] : 0;
    int s = v;
    #pragma unroll
    for (int off = 16; off > 0; off >>= 1)
        s += __shfl_down_sync(0xffffffffu, s, off);
    if (lane == 0) wsum[w] = s;
    __syncthreads();
    if (w == 0) {
        int t = wsum[lane];
        #pragma unroll
        for (int off = 16; off > 0; off >>= 1)
            t += __shfl_down_sync(0xffffffffu, t, off);
        if (lane == 0) g_bsum[blockIdx.x] = t;
    }
}

__global__ void scan2_kernel() {
    int tid = threadIdx.x;  // 64 threads
    int v = (tid < SCAN_B) ? g_bsum[tid] : 0;
    __shared__ int tmp[64];
    int lane = tid & 31, w = tid >> 5;
    int incl = v;
    #pragma unroll
    for (int off = 1; off < 32; off <<= 1) {
        int t = __shfl_up_sync(0xffffffffu, incl, off);
        if (lane >= off) incl += t;
    }
    tmp[tid] = incl;
    __syncthreads();
    int add = (w == 1) ? tmp[31] : 0;
    int excl = incl - v + add;
    if (tid < SCAN_B) g_boff[tid] = excl;
}

__global__ __launch_bounds__(1024) void scan3_kernel() {
    __shared__ int wsum[32];
    int tid = threadIdx.x, lane = tid & 31, w = tid >> 5;
    int i = blockIdx.x * 1024 + tid;
    int v = (i < N_NODES) ? g_cnt[i] : 0;
    int incl = v;
    #pragma unroll
    for (int off = 1; off < 32; off <<= 1) {
        int t = __shfl_up_sync(0xffffffffu, incl, off);
        if (lane >= off) incl += t;
    }
    if (lane == 31) wsum[w] = incl;
    __syncthreads();
    if (w == 0) {
        int s = wsum[lane];
        #pragma unroll
        for (int off = 1; off < 32; off <<= 1) {
            int t = __shfl_up_sync(0xffffffffu, s, off);
            if (lane >= off) s += t;
        }
        wsum[lane] = s;
    }
    __syncthreads();
    int pref = (w > 0) ? wsum[w - 1] : 0;
    int inclTot = incl + pref + g_boff[blockIdx.x];
    if (i < N_NODES) {
        g_rowptr[i + 1] = inclTot;
        g_cursor[i] = inclTot - v;
        g_dinv[i] = rsqrtf((float)v + 1.0f);
        if (i == 0) g_rowptr[0] = 0;
    }
}

// ---------------- CSR fill ----------------
__global__ __launch_bounds__(512) void fill_kernel(const void* __restrict__ ei) {
    int e = blockIdx.x * blockDim.x + threadIdx.x;
    if (e < N_EDGES) {
        int src = load_idx(ei, e);
        int dst = load_idx(ei, N_EDGES + e);
        int pos = atomicAdd(&g_cursor[dst], 1);
        g_col[pos] = src;
    }
}

// ---------------- HMMA GEMM: g_t = A @ W, bf16 3-term split ---------------
// Block: 256 threads = 8 warps (4 m-groups x 2 n-halves). Tile 128x128.
// 4 K-phases of 32. A smem rows padded to 80 B, W rows to 272 B (LDSM-safe).
__global__ __launch_bounds__(256) void mma_gemm_kernel(const float* __restrict__ Ain,
                                                       const float* __restrict__ W) {
    const float* A = Ain ? Ain : g_h;
    __shared__ __align__(16) uint8_t sAhi[128 * 80];
    __shared__ __align__(16) uint8_t sAlo[128 * 80];
    __shared__ __align__(16) uint8_t sWhi[32 * 272];
    __shared__ __align__(16) uint8_t sWlo[32 * 272];

    int tid  = threadIdx.x;
    int wid  = tid >> 5, lane = tid & 31;
    int wm   = wid >> 1, wn = wid & 1;
    int gid  = lane >> 2, tig = lane & 3;
    int row0 = blockIdx.x * 128;

    uint32_t aAhi = smem_u32(sAhi), aAlo = smem_u32(sAlo);
    uint32_t aWhi = smem_u32(sWhi), aWlo = smem_u32(sWlo);

    float c[2][8][4];
    #pragma unroll
    for (int mt = 0; mt < 2; ++mt)
        #pragma unroll
        for (int j = 0; j < 8; ++j)
            #pragma unroll
            for (int q = 0; q < 4; ++q) c[mt][j][q] = 0.f;

    // per-lane ldmatrix source addresses (t = lane>>3, r = lane&7)
    int t = lane >> 3, r = lane & 7;
    // A: tile order (mlo,klo),(mhi,klo),(mlo,khi),(mhi,khi)
    int a_m  = wm * 32 + (t & 1) * 8 + r;     // + mt*16 at use site
    int a_k  = (t >> 1) * 8;                  // + kk at use site
    // B(.trans): tile order (klo,j),(khi,j),(klo,j+1),(khi,j+1)
    int b_k  = (t & 1) * 8 + r;               // + kk
    int b_n  = wn * 64 + (t >> 1) * 8;        // + j*8

    for (int p = 0; p < 4; ++p) {
        // ---- stage A slice (128 x 32) as hi/lo bf16 ----
        #pragma unroll
        for (int i = 0; i < 4; ++i) {
            int idx = tid + i * 256;          // 0..1023
            int m = idx >> 3, kq = idx & 7;
            int row = row0 + m;
            float4 a = (row < N_NODES)
                ? *(const float4*)&A[(size_t)row * DIM + p * 32 + kq * 4]
                : make_float4(0.f, 0.f, 0.f, 0.f);
            uint32_t h0 = cvt_bf16x2(a.y, a.x);
            uint32_t h1 = cvt_bf16x2(a.w, a.z);
            float bx = __uint_as_float(h0 << 16);
            float by = __uint_as_float(h0 & 0xffff0000u);
            float bz = __uint_as_float(h1 << 16);
            float bw = __uint_as_float(h1 & 0xffff0000u);
            uint32_t l0 = cvt_bf16x2(a.y - by, a.x - bx);
            uint32_t l1 = cvt_bf16x2(a.w - bw, a.z - bz);
            uint32_t off = (uint32_t)(m * 80 + kq * 8);
            *(uint2*)(sAhi + off) = make_uint2(h0, h1);
            *(uint2*)(sAlo + off) = make_uint2(l0, l1);
        }
        // ---- stage W slice (32 x 128) as hi/lo bf16, k-major rows ----
        #pragma unroll
        for (int i = 0; i < 4; ++i) {
            int idx = tid + i * 256;          // 0..1023
            int k = idx >> 5, nq = idx & 31;
            float4 w = *(const float4*)&W[(size_t)(p * 32 + k) * DIM + nq * 4];
            uint32_t h0 = cvt_bf16x2(w.y, w.x);
            uint32_t h1 = cvt_bf16x2(w.w, w.z);
            float bx = __uint_as_float(h0 << 16);
            float by = __uint_as_float(h0 & 0xffff0000u);
            float bz = __uint_as_float(h1 << 16);
            float bw = __uint_as_float(h1 & 0xffff0000u);
            uint32_t l0 = cvt_bf16x2(w.y - by, w.x - bx);
            uint32_t l1 = cvt_bf16x2(w.w - bw, w.z - bz);
            uint32_t off = (uint32_t)(k * 272 + nq * 8);
            *(uint2*)(sWhi + off) = make_uint2(h0, h1);
            *(uint2*)(sWlo + off) = make_uint2(l0, l1);
        }
        __syncthreads();

        #pragma unroll
        for (int kk = 0; kk < 32; kk += 16) {
            uint32_t ahi[2][4], alo[2][4];
            #pragma unroll
            for (int mt = 0; mt < 2; ++mt) {
                uint32_t ao = (uint32_t)((a_m + mt * 16) * 80 + (kk + a_k) * 2);
                ldsm_x4(ahi[mt], aAhi + ao);
                ldsm_x4(alo[mt], aAlo + ao);
            }
            #pragma unroll
            for (int j = 0; j < 8; j += 2) {
                uint32_t bo = (uint32_t)((kk + b_k) * 272 + (b_n + j * 8) * 2);
                uint32_t bh[4], bl[4];
                ldsm_x4_t(bh, aWhi + bo);
                ldsm_x4_t(bl, aWlo + bo);
                #pragma unroll
                for (int mt = 0; mt < 2; ++mt) {
                    mma_bf16(c[mt][j],     ahi[mt], bh[0], bh[1]);
                    mma_bf16(c[mt][j],     alo[mt], bh[0], bh[1]);
                    mma_bf16(c[mt][j],     ahi[mt], bl[0], bl[1]);
                    mma_bf16(c[mt][j + 1], ahi[mt], bh[2], bh[3]);
                    mma_bf16(c[mt][j + 1], alo[mt], bh[2], bh[3]);
                    mma_bf16(c[mt][j + 1], ahi[mt], bl[2], bl[3]);
                }
            }
        }
        __syncthreads();
    }

    // ---- epilogue: fragments -> g_t ----
    #pragma unroll
    for (int mt = 0; mt < 2; ++mt) {
        int rrow = row0 + wm * 32 + mt * 16 + gid;
        #pragma unroll
        for (int j = 0; j < 8; ++j) {
            int col = wn * 64 + j * 8 + 2 * tig;
            if (rrow < N_NODES)
                *(float2*)&g_t[(size_t)rrow * DIM + col] =
                    make_float2(c[mt][j][0], c[mt][j][1]);
            if (rrow + 8 < N_NODES)
                *(float2*)&g_t[(size_t)(rrow + 8) * DIM + col] =
                    make_float2(c[mt][j][2], c[mt][j][3]);
        }
    }
}

// ---------------- aggregation: warp-per-node, float4 gathers --------------
__global__ __launch_bounds__(256) void agg_kernel(const float* __restrict__ bias) {
    int warp = threadIdx.x >> 5;
    int lane = threadIdx.x & 31;
    int i = blockIdx.x * 8 + warp;

    float di = g_dinv[i];
    const float4 tself = *(const float4*)&g_t[(size_t)i * DIM + lane * 4];
    float4 acc;
    acc.x = di * di * tself.x;
    acc.y = di * di * tself.y;
    acc.z = di * di * tself.z;
    acc.w = di * di * tself.w;

    int s = g_rowptr[i], e = g_rowptr[i + 1];
    for (int base = s; base < e; base += 32) {
        int n = min(32, e - base);
        int c = 0; float wgt = 0.f;
        if (lane < n) {
            c = g_col[base + lane];
            wgt = g_dinv[c] * di;
        }
        #pragma unroll 8
        for (int j = 0; j < n; ++j) {
            int   cj = __shfl_sync(0xffffffffu, c, j);
            float wj = __shfl_sync(0xffffffffu, wgt, j);
            const float4 v = *(const float4*)&g_t[(size_t)cj * DIM + lane * 4];
            acc.x = fmaf(wj, v.x, acc.x);
            acc.y = fmaf(wj, v.y, acc.y);
            acc.z = fmaf(wj, v.z, acc.z);
            acc.w = fmaf(wj, v.w, acc.w);
        }
    }

    const float4 b4 = *(const float4*)&bias[lane * 4];
    float4 r;
    r.x = fmaxf(acc.x + b4.x, 0.f);
    r.y = fmaxf(acc.y + b4.y, 0.f);
    r.z = fmaxf(acc.z + b4.z, 0.f);
    r.w = fmaxf(acc.w + b4.w, 0.f);
    *(float4*)&g_h[(size_t)i * DIM + lane * 4] = r;
}

// ---------------- fused pool + linear + L2 normalize ----------------------
__global__ __launch_bounds__(128) void poolfinal_kernel(const void* __restrict__ batch,
                                                        const float* __restrict__ Wl,
                                                        const float* __restrict__ bl,
                                                        float* __restrict__ out) {
    int g = blockIdx.x;
    int tid = threadIdx.x;
    __shared__ int s_lo, s_hi;
    __shared__ float mean[DIM];
    __shared__ float outv[OUTD];
    __shared__ float red[OUTD];

    if (tid == 0 || tid == 1) {
        int target = g + tid;
        int lo = 0, hi = N_NODES;
        while (lo < hi) {
            int mid = (lo + hi) >> 1;
            if (load_idx(batch, mid) < target) lo = mid + 1;
            else hi = mid;
        }
        if (tid == 0) s_lo = lo; else s_hi = lo;
    }
    __syncthreads();
    int lo = s_lo, hi = s_hi;

    float s0 = 0.f, s1 = 0.f, s2 = 0.f, s3 = 0.f;
    int n = lo;
    for (; n + 4 <= hi; n += 4) {
        s0 += g_h[(size_t)(n + 0) * DIM + tid];
        s1 += g_h[(size_t)(n + 1) * DIM + tid];
        s2 += g_h[(size_t)(n + 2) * DIM + tid];
        s3 += g_h[(size_t)(n + 3) * DIM + tid];
    }
    for (; n < hi; ++n) s0 += g_h[(size_t)n * DIM + tid];
    float sum = (s0 + s1) + (s2 + s3);
    float cn = fmaxf((float)(hi - lo), 1.f);
    mean[tid] = sum / cn;
    __syncthreads();

    if (tid < OUTD) {
        float acc = bl[tid];
        #pragma unroll
        for (int h = 0; h < DIM; ++h)
            acc = fmaf(mean[h], Wl[h * OUTD + tid], acc);
        outv[tid] = acc;
        red[tid]  = acc * acc;
    }
    __syncthreads();
    for (int s = 32; s > 0; s >>= 1) {
        if (tid < s && tid + s < OUTD) red[tid] += red[tid + s];
        __syncthreads();
    }
    if (tid < OUTD) {
        float nrm = sqrtf(red[0]);
        out[g * OUTD + tid] = outv[tid] / fmaxf(nrm, 1e-12f);
    }
}

// ---------------- launch ----------------
extern "C" void kernel_launch(void* const* d_in, const int* in_sizes, int n_in,
                              void* d_out, int out_size) {
    const float* x     = (const float*)d_in[0];
    const float* W1    = (const float*)d_in[1];
    const float* b1    = (const float*)d_in[2];
    const float* W2    = (const float*)d_in[3];
    const float* b2    = (const float*)d_in[4];
    const float* Wl    = (const float*)d_in[5];
    const float* bl    = (const float*)d_in[6];
    const void*  ei    = d_in[7];
    const void*  batch = d_in[8];
    float* out = (float*)d_out;

    init_kernel<<<(N_NODES + 255) / 256, 256>>>(ei);
    count_kernel<<<(N_EDGES + 511) / 512, 512>>>(ei);
    scan1_kernel<<<SCAN_B, 1024>>>();
    scan2_kernel<<<1, 64>>>();
    scan3_kernel<<<SCAN_B, 1024>>>();
    fill_kernel<<<(N_EDGES + 511) / 512, 512>>>(ei);

    // layer 1
    mma_gemm_kernel<<<GTILES, 256>>>(x, W1);
    agg_kernel<<<N_NODES / 8, 256>>>(b1);
    // layer 2
    mma_gemm_kernel<<<GTILES, 256>>>(nullptr, W2);
    agg_kernel<<<N_NODES / 8, 256>>>(b2);

    poolfinal_kernel<<<NGRAPH, 128>>>(batch, Wl, bl, out);
}